// round 7
// baseline (speedup 1.0000x reference)
#include <cuda_runtime.h>
#include <cstdint>

#define S_DIM 2048
#define QT 16
#define KT 128
#define NTHR 512
#define SCS 2052           // score row stride (words), mod 32 = 4
#define KBS 68             // K tile row stride (words)
#define OUT_O_ELEMS 4194304ull

// word offsets in dynamic smem
#define SCW 0                       // 16*2052           = 32832 w
#define KBW 32832                   // 2*128*68          = 17408 w
#define QSW (KBW + 17408)           // 16*68             = 1088 w
#define REDW (QSW + 1088)           // 16*16             = 256 w
#define INVW (REDW + 256)           // 16 w
#define SM_BYTES ((INVW + 16) * 4)  // 206464 B

__device__ __forceinline__ uint32_t smem_u32(const void* p) {
  uint32_t a;
  asm("{ .reg .u64 t; cvta.to.shared.u64 t, %1; cvt.u32.u64 %0, t; }" : "=r"(a) : "l"(p));
  return a;
}
__device__ __forceinline__ float tf32f(float x) {
  uint32_t u; asm("cvt.rna.tf32.f32 %0, %1;" : "=r"(u) : "f"(x));
  return __uint_as_float(u);
}
__device__ __forceinline__ void mma8(float c[4], const uint32_t a[4],
                                     uint32_t b0, uint32_t b1) {
  asm volatile("mma.sync.aligned.m16n8k8.row.col.f32.tf32.tf32.f32 "
    "{%0,%1,%2,%3}, {%4,%5,%6,%7}, {%8,%9}, {%0,%1,%2,%3};"
    : "+f"(c[0]), "+f"(c[1]), "+f"(c[2]), "+f"(c[3])
    : "r"(a[0]), "r"(a[1]), "r"(a[2]), "r"(a[3]), "r"(b0), "r"(b1));
}
#define CP16(dst, src) asm volatile("cp.async.ca.shared.global [%0], [%1], 16;" :: "r"(dst), "l"(src) : "memory")
#define CP_COMMIT()    asm volatile("cp.async.commit_group;" ::: "memory")
#define CP_WAIT0()     asm volatile("cp.async.wait_group 0;" ::: "memory")

__global__ void __launch_bounds__(NTHR, 1)
attn_mma_kernel(const float* __restrict__ Q, const float* __restrict__ K,
                const float* __restrict__ V, float* __restrict__ out) {
  extern __shared__ __align__(16) float smf[];
  const uint32_t sb = smem_u32(smf);
  const int tid = threadIdx.x;
  const int w = tid >> 5, lane = tid & 31;
  const int gid = lane >> 2, tg = lane & 3;
  const int bh = blockIdx.y;
  const int qt = (int)gridDim.x - 1 - (int)blockIdx.x;   // heavy tiles first
  const int q0 = qt * QT;

  const float* Qg = Q + ((size_t)bh * S_DIM + q0) * 64;
  const float* Kg = K + (size_t)bh * S_DIM * 64;
  const float* Vg = V + (size_t)bh * S_DIM * 64;
  float* Og = out + ((size_t)bh * S_DIM + q0) * 64;
  float* Wg = out + OUT_O_ELEMS + ((size_t)bh * S_DIM + q0) * (size_t)S_DIM;

  const int nkt = (q0 + QT + KT - 1) >> 7;

  // ---- stage Q (x 1/8, rna-tf32) ----
  if (tid < 256) {
    int r = tid >> 4, f = tid & 15;
    float4 v = ((const float4*)Qg)[r * 16 + f];
    float* d = &smf[QSW + r * KBS + 4 * f];
    d[0] = tf32f(v.x * 0.125f); d[1] = tf32f(v.y * 0.125f);
    d[2] = tf32f(v.z * 0.125f); d[3] = tf32f(v.w * 0.125f);
  }
  // ---- prolog: prefetch K tile 0 (raw fp32) ----
  {
    const char* kg0 = (const char*)Kg;
    #pragma unroll
    for (int it = 0; it < 4; ++it) {
      int idx = tid + it * NTHR;           // 2048 16B chunks
      int r = idx >> 4, c = idx & 15;
      CP16(sb + KBW * 4 + r * (KBS * 4) + c * 16, kg0 + r * 256 + c * 16);
    }
    CP_COMMIT();
  }
  __syncthreads();

  // ---- hoist Q A-fragments ----
  uint32_t af[8][4];
  #pragma unroll
  for (int s = 0; s < 8; ++s) {
    af[s][0] = __float_as_uint(smf[QSW + gid * KBS + s * 8 + tg]);
    af[s][1] = __float_as_uint(smf[QSW + (gid + 8) * KBS + s * 8 + tg]);
    af[s][2] = __float_as_uint(smf[QSW + gid * KBS + s * 8 + tg + 4]);
    af[s][3] = __float_as_uint(smf[QSW + (gid + 8) * KBS + s * 8 + tg + 4]);
  }

  float rs0 = 0.f, rs1 = 0.f;
  float oc[8][4];
  #pragma unroll
  for (int j = 0; j < 8; ++j)
    #pragma unroll
    for (int u = 0; u < 4; ++u) oc[j][u] = 0.f;

  const int r0 = q0 + gid, r1 = r0 + 8;

  for (int tt = 0; tt < nkt; ++tt) {
    const int kc = tt << 7;
    CP_WAIT0();
    __syncthreads();           // K(tt) visible; everyone done with kbuf[(tt-1)&1]

    // ---- prefetch V for THIS tile into registers (latency hidden by QK) ----
    const int kcb = kc + w * 8;
    const float* vr = Vg + (size_t)kcb * 64;
    uint32_t vpre[16];
    #pragma unroll
    for (int j = 0; j < 8; ++j) {
      vpre[j]     = __float_as_uint(vr[tg * 64 + j * 8 + gid]);
      vpre[8 + j] = __float_as_uint(vr[(tg + 4) * 64 + j * 8 + gid]);
    }

    if (tt + 1 < nkt) {        // prefetch K(tt+1) into the other buffer
      const char* kg1 = (const char*)(Kg + (size_t)(kc + KT) * 64);
      uint32_t dstb = sb + (KBW + ((tt + 1) & 1) * KT * KBS) * 4;
      #pragma unroll
      for (int it = 0; it < 4; ++it) {
        int idx = tid + it * NTHR;
        int r = idx >> 4, c = idx & 15;
        CP16(dstb + r * (KBS * 4) + c * 16, kg1 + r * 256 + c * 16);
      }
      CP_COMMIT();
    }
    const float* kb = &smf[KBW + (tt & 1) * KT * KBS];

    // ---- QK: warp's own n8 strip, two independent 4-MMA chains ----
    float acca[4] = {0.f, 0.f, 0.f, 0.f};
    float accb[4] = {0.f, 0.f, 0.f, 0.f};
    const int ncol = w * 8 + gid;
    #pragma unroll
    for (int s = 0; s < 4; ++s) {
      uint32_t b0 = __float_as_uint(tf32f(kb[ncol * KBS + s * 8 + tg]));
      uint32_t b1 = __float_as_uint(tf32f(kb[ncol * KBS + s * 8 + tg + 4]));
      mma8(acca, af[s], b0, b1);
      uint32_t c0 = __float_as_uint(tf32f(kb[ncol * KBS + (s + 4) * 8 + tg]));
      uint32_t c1 = __float_as_uint(tf32f(kb[ncol * KBS + (s + 4) * 8 + tg + 4]));
      mma8(accb, af[s + 4], c0, c1);
    }
    acca[0] += accb[0]; acca[1] += accb[1];
    acca[2] += accb[2]; acca[3] += accb[3];

    // ---- mask + exp + store p~ + row-sum ----
    const int cg = kc + w * 8 + 2 * tg;
    {
      float e00 = (cg     <= r0) ? tf32f(__expf(acca[0])) : 0.f;
      float e01 = (cg + 1 <= r0) ? tf32f(__expf(acca[1])) : 0.f;
      float e10 = (cg     <= r1) ? tf32f(__expf(acca[2])) : 0.f;
      float e11 = (cg + 1 <= r1) ? tf32f(__expf(acca[3])) : 0.f;
      rs0 += e00 + e01; rs1 += e10 + e11;
      *(float2*)&smf[SCW + gid * SCS + cg]       = make_float2(e00, e01);
      *(float2*)&smf[SCW + (gid + 8) * SCS + cg] = make_float2(e10, e11);
    }
    __syncwarp();   // warp-local: A-frag reads below only touch this warp's stores

    // ---- A-fragments (p~) in PV layout, conflict-free LDS ----
    uint32_t pa[4];
    pa[0] = __float_as_uint(smf[SCW + gid * SCS + kcb + tg]);
    pa[1] = __float_as_uint(smf[SCW + (gid + 8) * SCS + kcb + tg]);
    pa[2] = __float_as_uint(smf[SCW + gid * SCS + kcb + tg + 4]);
    pa[3] = __float_as_uint(smf[SCW + (gid + 8) * SCS + kcb + tg + 4]);

    // ---- PV: warp's k8 slice x all 64 d-cols, V from prefetched regs ----
    #pragma unroll
    for (int j = 0; j < 8; ++j) {
      uint32_t b0 = __float_as_uint(tf32f(__uint_as_float(vpre[j])));
      uint32_t b1 = __float_as_uint(tf32f(__uint_as_float(vpre[8 + j])));
      mma8(oc[j], pa, b0, b1);
    }
  }

  // ---- row-sum reduce -> inv ----
  rs0 += __shfl_xor_sync(~0u, rs0, 1); rs0 += __shfl_xor_sync(~0u, rs0, 2);
  rs1 += __shfl_xor_sync(~0u, rs1, 1); rs1 += __shfl_xor_sync(~0u, rs1, 2);
  if (tg == 0) { smf[REDW + w * 16 + gid] = rs0; smf[REDW + w * 16 + gid + 8] = rs1; }
  __syncthreads();
  if (tid < 16) {
    float s = 0.f;
    #pragma unroll
    for (int i = 0; i < 16; ++i) s += smf[REDW + i * 16 + tid];
    smf[INVW + tid] = 1.0f / s;
  }
  __syncthreads();

  // ---- W sweep: p~ * inv, then zero-fill tail ----
  {
    const int ktend = nkt * KT;
    const int r = tid >> 5, f = tid & 31;
    const float iv = smf[INVW + r];
    float4* wrow = (float4*)(Wg + (size_t)r * S_DIM);
    int c4 = f;
    for (; c4 < (ktend >> 2); c4 += 32) {
      float4 v = *(float4*)&smf[SCW + r * SCS + 4 * c4];
      v.x *= iv; v.y *= iv; v.z *= iv; v.w *= iv;
      wrow[c4] = v;
    }
    const float4 z = make_float4(0.f, 0.f, 0.f, 0.f);
    for (; c4 < (S_DIM >> 2); c4 += 32) wrow[c4] = z;
  }
  __syncthreads();   // sc free now — reuse as O-merge scratch

  // ---- O merge: 16 per-warp partials -> O ----
  {
    float* osc = &smf[SCW + w * (16 * KBS)];
    #pragma unroll
    for (int j = 0; j < 8; ++j) {
      *(float2*)&osc[gid * KBS + j * 8 + 2 * tg]       = make_float2(oc[j][0], oc[j][1]);
      *(float2*)&osc[(gid + 8) * KBS + j * 8 + 2 * tg] = make_float2(oc[j][2], oc[j][3]);
    }
  }
  __syncthreads();
  {
    #pragma unroll
    for (int e = tid; e < 1024; e += NTHR) {
      const int r = e >> 6, d = e & 63;
      float s = 0.f;
      #pragma unroll
      for (int p = 0; p < 16; ++p) s += smf[SCW + p * (16 * KBS) + r * KBS + d];
      Og[r * 64 + d] = s * smf[INVW + r];
    }
  }
}

extern "C" void kernel_launch(void* const* d_in, const int* in_sizes, int n_in,
                              void* d_out, int out_size) {
  (void)in_sizes; (void)n_in; (void)out_size;
  const float* q = (const float*)d_in[0];
  const float* k = (const float*)d_in[1];
  const float* v = (const float*)d_in[2];
  float* out = (float*)d_out;

  cudaFuncSetAttribute(attn_mma_kernel,
                       cudaFuncAttributeMaxDynamicSharedMemorySize, SM_BYTES);
  dim3 grid(S_DIM / QT, 32);
  attn_mma_kernel<<<grid, NTHR, SM_BYTES>>>(q, k, v, out);
}

// round 8
// speedup vs baseline: 1.6162x; 1.6162x over previous
#include <cuda_runtime.h>
#include <cstdint>

#define S_DIM 2048
#define QT 16
#define KT 64
#define NTHR 256
#define KBS 68             // K/V tile row stride (words)
#define OUT_O_ELEMS 4194304ull

__device__ float g_inv[65536];   // 1/rowsum per (bh, row), pass A -> pass B

__device__ __forceinline__ uint32_t smem_u32(const void* p) {
  uint32_t a;
  asm("{ .reg .u64 t; cvta.to.shared.u64 t, %1; cvt.u32.u64 %0, t; }" : "=r"(a) : "l"(p));
  return a;
}
__device__ __forceinline__ float tf32f(float x) {
  uint32_t u; asm("cvt.rna.tf32.f32 %0, %1;" : "=r"(u) : "f"(x));
  return __uint_as_float(u);
}
__device__ __forceinline__ void mma8(float c[4], const uint32_t a[4],
                                     uint32_t b0, uint32_t b1) {
  asm volatile("mma.sync.aligned.m16n8k8.row.col.f32.tf32.tf32.f32 "
    "{%0,%1,%2,%3}, {%4,%5,%6,%7}, {%8,%9}, {%0,%1,%2,%3};"
    : "+f"(c[0]), "+f"(c[1]), "+f"(c[2]), "+f"(c[3])
    : "r"(a[0]), "r"(a[1]), "r"(a[2]), "r"(a[3]), "r"(b0), "r"(b1));
}
#define CP16(dst, src) asm volatile("cp.async.ca.shared.global [%0], [%1], 16;" :: "r"(dst), "l"(src) : "memory")
#define CP_COMMIT()    asm volatile("cp.async.commit_group;" ::: "memory")
#define CP_WAIT0()     asm volatile("cp.async.wait_group 0;" ::: "memory")

// ======================= PASS A : row sums =======================
#define A_QSW 0
#define A_KBW 1088                      // 2*64*68 = 8704 w
#define A_REDW (A_KBW + 2 * KT * KBS)   // 9792
#define A_SMB ((A_REDW + 128) * 4)      // 39680 B

__global__ void __launch_bounds__(NTHR, 3)
rowsum_kernel(const float* __restrict__ Q, const float* __restrict__ K) {
  extern __shared__ __align__(16) float smf[];
  const uint32_t sb = smem_u32(smf);
  const int tid = threadIdx.x;
  const int w = tid >> 5, lane = tid & 31;
  const int gid = lane >> 2, tg = lane & 3;
  const int bh = blockIdx.y;
  const int qt = (int)gridDim.x - 1 - (int)blockIdx.x;
  const int q0 = qt * QT;

  const float* Qg = Q + ((size_t)bh * S_DIM + q0) * 64;
  const float* Kg = K + (size_t)bh * S_DIM * 64;

  { // stage Q (x 1/8, rna-tf32): 16 rows x 16 chunks = 256 threads
    int r = tid >> 4, f = tid & 15;
    float4 v = ((const float4*)Qg)[tid];
    float* d = &smf[A_QSW + r * KBS + 4 * f];
    d[0] = tf32f(v.x * 0.125f); d[1] = tf32f(v.y * 0.125f);
    d[2] = tf32f(v.z * 0.125f); d[3] = tf32f(v.w * 0.125f);
  }
  { // prolog: K tile 0
    const char* kg0 = (const char*)Kg;
    #pragma unroll
    for (int it = 0; it < 4; ++it) {
      int idx = tid + it * NTHR;          // 1024 16B chunks
      int r = idx >> 4, c = idx & 15;
      CP16(sb + (A_KBW + r * KBS) * 4 + c * 16, kg0 + r * 256 + c * 16);
    }
    CP_COMMIT();
  }
  __syncthreads();

  uint32_t af[8][4];
  #pragma unroll
  for (int s = 0; s < 8; ++s) {
    af[s][0] = __float_as_uint(smf[A_QSW + gid * KBS + s * 8 + tg]);
    af[s][1] = __float_as_uint(smf[A_QSW + (gid + 8) * KBS + s * 8 + tg]);
    af[s][2] = __float_as_uint(smf[A_QSW + gid * KBS + s * 8 + tg + 4]);
    af[s][3] = __float_as_uint(smf[A_QSW + (gid + 8) * KBS + s * 8 + tg + 4]);
  }

  const int nkt = (q0 + QT + KT - 1) >> 6;
  const int r0 = q0 + gid, r1 = r0 + 8;
  float rs0 = 0.f, rs1 = 0.f;

  for (int tt = 0; tt < nkt; ++tt) {
    const int kc = tt << 6;
    CP_WAIT0();
    __syncthreads();
    if (tt + 1 < nkt) {
      const char* kg1 = (const char*)(Kg + (size_t)(kc + KT) * 64);
      uint32_t dstb = sb + (A_KBW + ((tt + 1) & 1) * KT * KBS) * 4;
      #pragma unroll
      for (int it = 0; it < 4; ++it) {
        int idx = tid + it * NTHR;
        int r = idx >> 4, c = idx & 15;
        CP16(dstb + r * KBS * 4 + c * 16, kg1 + r * 256 + c * 16);
      }
      CP_COMMIT();
    }
    const float* kb = &smf[A_KBW + (tt & 1) * KT * KBS];

    float acca[4] = {0.f, 0.f, 0.f, 0.f};
    float accb[4] = {0.f, 0.f, 0.f, 0.f};
    const int ncol = w * 8 + gid;
    #pragma unroll
    for (int s = 0; s < 4; ++s) {
      uint32_t b0 = __float_as_uint(tf32f(kb[ncol * KBS + s * 8 + tg]));
      uint32_t b1 = __float_as_uint(tf32f(kb[ncol * KBS + s * 8 + tg + 4]));
      mma8(acca, af[s], b0, b1);
      uint32_t c0 = __float_as_uint(tf32f(kb[ncol * KBS + (s + 4) * 8 + tg]));
      uint32_t c1 = __float_as_uint(tf32f(kb[ncol * KBS + (s + 4) * 8 + tg + 4]));
      mma8(accb, af[s + 4], c0, c1);
    }
    const int cg = kc + w * 8 + 2 * tg;
    rs0 += ((cg     <= r0) ? __expf(acca[0] + accb[0]) : 0.f)
         + ((cg + 1 <= r0) ? __expf(acca[1] + accb[1]) : 0.f);
    rs1 += ((cg     <= r1) ? __expf(acca[2] + accb[2]) : 0.f)
         + ((cg + 1 <= r1) ? __expf(acca[3] + accb[3]) : 0.f);
  }

  rs0 += __shfl_xor_sync(~0u, rs0, 1); rs0 += __shfl_xor_sync(~0u, rs0, 2);
  rs1 += __shfl_xor_sync(~0u, rs1, 1); rs1 += __shfl_xor_sync(~0u, rs1, 2);
  if (tg == 0) { smf[A_REDW + w * 16 + gid] = rs0; smf[A_REDW + w * 16 + gid + 8] = rs1; }
  __syncthreads();
  if (tid < 16) {
    float s = 0.f;
    #pragma unroll
    for (int i = 0; i < 8; ++i) s += smf[A_REDW + i * 16 + tid];
    g_inv[bh * S_DIM + q0 + tid] = 1.0f / s;
  }
}

// ======================= PASS B : W + O =======================
#define B_QSW 0
#define B_KBW 1088
#define B_VBW (B_KBW + 2 * KT * KBS)    // 9792
#define B_SMB ((B_VBW + 2 * KT * KBS) * 4)  // 73984 B

__global__ void __launch_bounds__(NTHR, 2)
attn_pb_kernel(const float* __restrict__ Q, const float* __restrict__ K,
               const float* __restrict__ V, float* __restrict__ out) {
  extern __shared__ __align__(16) float smf[];
  const uint32_t sb = smem_u32(smf);
  const int tid = threadIdx.x;
  const int w = tid >> 5, lane = tid & 31;
  const int gid = lane >> 2, tg = lane & 3;
  const int bh = blockIdx.y;
  const int qt = (int)gridDim.x - 1 - (int)blockIdx.x;
  const int q0 = qt * QT;

  const float* Qg = Q + ((size_t)bh * S_DIM + q0) * 64;
  const float* Kg = K + (size_t)bh * S_DIM * 64;
  const float* Vg = V + (size_t)bh * S_DIM * 64;
  float* Og = out + ((size_t)bh * S_DIM + q0) * 64;
  float* Wg = out + OUT_O_ELEMS + ((size_t)bh * S_DIM + q0) * (size_t)S_DIM;

  const float iv0 = g_inv[bh * S_DIM + q0 + gid];
  const float iv1 = g_inv[bh * S_DIM + q0 + gid + 8];

  { // stage Q
    int r = tid >> 4, f = tid & 15;
    float4 v = ((const float4*)Qg)[tid];
    float* d = &smf[B_QSW + r * KBS + 4 * f];
    d[0] = tf32f(v.x * 0.125f); d[1] = tf32f(v.y * 0.125f);
    d[2] = tf32f(v.z * 0.125f); d[3] = tf32f(v.w * 0.125f);
  }
  { // prolog: K+V tile 0.  V chunk swizzle: word col (4c + 4r) & 63
    const char* kg0 = (const char*)Kg;
    const char* vg0 = (const char*)Vg;
    #pragma unroll
    for (int it = 0; it < 4; ++it) {
      int idx = tid + it * NTHR;
      int r = idx >> 4, c = idx & 15;
      CP16(sb + (B_KBW + r * KBS) * 4 + c * 16, kg0 + r * 256 + c * 16);
      CP16(sb + (B_VBW + r * KBS + (((c << 2) + (r << 2)) & 63)) * 4, vg0 + r * 256 + c * 16);
    }
    CP_COMMIT();
  }
  __syncthreads();

  uint32_t af[8][4];
  #pragma unroll
  for (int s = 0; s < 8; ++s) {
    af[s][0] = __float_as_uint(smf[B_QSW + gid * KBS + s * 8 + tg]);
    af[s][1] = __float_as_uint(smf[B_QSW + (gid + 8) * KBS + s * 8 + tg]);
    af[s][2] = __float_as_uint(smf[B_QSW + gid * KBS + s * 8 + tg + 4]);
    af[s][3] = __float_as_uint(smf[B_QSW + (gid + 8) * KBS + s * 8 + tg + 4]);
  }

  const int nkt = (q0 + QT + KT - 1) >> 6;
  const int r0 = q0 + gid, r1 = r0 + 8;
  float oc[8][4];
  #pragma unroll
  for (int j = 0; j < 8; ++j)
    #pragma unroll
    for (int u = 0; u < 4; ++u) oc[j][u] = 0.f;

  for (int tt = 0; tt < nkt; ++tt) {
    const int kc = tt << 6;
    CP_WAIT0();
    __syncthreads();
    if (tt + 1 < nkt) {
      const char* kg1 = (const char*)(Kg + (size_t)(kc + KT) * 64);
      const char* vg1 = (const char*)(Vg + (size_t)(kc + KT) * 64);
      uint32_t kd = sb + (B_KBW + ((tt + 1) & 1) * KT * KBS) * 4;
      uint32_t vd = sb + (B_VBW + ((tt + 1) & 1) * KT * KBS) * 4;
      #pragma unroll
      for (int it = 0; it < 4; ++it) {
        int idx = tid + it * NTHR;
        int r = idx >> 4, c = idx & 15;
        CP16(kd + r * KBS * 4 + c * 16, kg1 + r * 256 + c * 16);
        CP16(vd + (r * KBS + (((c << 2) + (r << 2)) & 63)) * 4, vg1 + r * 256 + c * 16);
      }
      CP_COMMIT();
    }
    const float* kb = &smf[B_KBW + (tt & 1) * KT * KBS];
    const float* vb = &smf[B_VBW + (tt & 1) * KT * KBS];

    // ---- QK: warp's n8 strip, two independent 4-MMA chains ----
    float acca[4] = {0.f, 0.f, 0.f, 0.f};
    float accb[4] = {0.f, 0.f, 0.f, 0.f};
    const int ncol = w * 8 + gid;
    #pragma unroll
    for (int s = 0; s < 4; ++s) {
      uint32_t b0 = __float_as_uint(tf32f(kb[ncol * KBS + s * 8 + tg]));
      uint32_t b1 = __float_as_uint(tf32f(kb[ncol * KBS + s * 8 + tg + 4]));
      mma8(acca, af[s], b0, b1);
      uint32_t c0 = __float_as_uint(tf32f(kb[ncol * KBS + (s + 4) * 8 + tg]));
      uint32_t c1 = __float_as_uint(tf32f(kb[ncol * KBS + (s + 4) * 8 + tg + 4]));
      mma8(accb, af[s + 4], c0, c1);
    }

    // ---- final p = mask ? exp(s)*inv : 0 ; write W straight from regs ----
    const int cg = kc + w * 8 + 2 * tg;
    float e00 = (cg     <= r0) ? __expf(acca[0] + accb[0]) * iv0 : 0.f;
    float e01 = (cg + 1 <= r0) ? __expf(acca[1] + accb[1]) * iv0 : 0.f;
    float e10 = (cg     <= r1) ? __expf(acca[2] + accb[2]) * iv1 : 0.f;
    float e11 = (cg + 1 <= r1) ? __expf(acca[3] + accb[3]) * iv1 : 0.f;
    *(float2*)&Wg[(size_t)gid * S_DIM + cg]       = make_float2(e00, e01);
    *(float2*)&Wg[(size_t)(gid + 8) * S_DIM + cg] = make_float2(e10, e11);

    // ---- rebuild PV A-fragment via shuffles (col 2tg' -> col tg layout) ----
    const int srcA = gid * 4 + (tg >> 1);
    const int srcB = srcA + 2;
    float a0 = __shfl_sync(~0u, e00, srcA), a1 = __shfl_sync(~0u, e01, srcA);
    float g0 = __shfl_sync(~0u, e10, srcA), g1 = __shfl_sync(~0u, e11, srcA);
    float h0 = __shfl_sync(~0u, e00, srcB), h1 = __shfl_sync(~0u, e01, srcB);
    float k0 = __shfl_sync(~0u, e10, srcB), k1 = __shfl_sync(~0u, e11, srcB);
    const bool odd = tg & 1;
    uint32_t pa[4];
    pa[0] = __float_as_uint(tf32f(odd ? a1 : a0));
    pa[1] = __float_as_uint(tf32f(odd ? g1 : g0));
    pa[2] = __float_as_uint(tf32f(odd ? h1 : h0));
    pa[3] = __float_as_uint(tf32f(odd ? k1 : k0));

    // ---- PV: warp's k8 slice x all 64 d-cols (V swizzled, conflict-free) ----
    const int kla = w * 8 + tg;          // b0 rows
    #pragma unroll
    for (int j = 0; j < 8; ++j) {
      const int dcol = j * 8 + gid;
      uint32_t b0 = __float_as_uint(tf32f(vb[kla * KBS + ((dcol + 4 * kla) & 63)]));
      uint32_t b1 = __float_as_uint(tf32f(vb[(kla + 4) * KBS + ((dcol + 4 * kla + 16) & 63)]));
      mma8(oc[j], pa, b0, b1);
    }
  }

  // ---- W zero tail ----
  {
    const int ktend = nkt * KT;
    const int r = tid >> 4, f = tid & 15;
    float4* wrow = (float4*)(Wg + (size_t)r * S_DIM);
    const float4 z = make_float4(0.f, 0.f, 0.f, 0.f);
    for (int c4 = (ktend >> 2) + f; c4 < (S_DIM >> 2); c4 += 16) wrow[c4] = z;
  }

  // ---- O merge: 8 per-warp k-partials (smem reuse; all loads/cp.async done) ----
  __syncthreads();
  {
    float* osc = &smf[w * (16 * 66)];
    #pragma unroll
    for (int j = 0; j < 8; ++j) {
      *(float2*)&osc[gid * 66 + j * 8 + 2 * tg]       = make_float2(oc[j][0], oc[j][1]);
      *(float2*)&osc[(gid + 8) * 66 + j * 8 + 2 * tg] = make_float2(oc[j][2], oc[j][3]);
    }
  }
  __syncthreads();
  #pragma unroll
  for (int it = 0; it < 4; ++it) {
    const int e = tid + it * NTHR;
    const int r = e >> 6, d = e & 63;
    float s = 0.f;
    #pragma unroll
    for (int p = 0; p < 8; ++p) s += smf[p * (16 * 66) + r * 66 + d];
    Og[r * 64 + d] = s;
  }
}

extern "C" void kernel_launch(void* const* d_in, const int* in_sizes, int n_in,
                              void* d_out, int out_size) {
  (void)in_sizes; (void)n_in; (void)out_size;
  const float* q = (const float*)d_in[0];
  const float* k = (const float*)d_in[1];
  const float* v = (const float*)d_in[2];
  float* out = (float*)d_out;

  cudaFuncSetAttribute(rowsum_kernel,
                       cudaFuncAttributeMaxDynamicSharedMemorySize, A_SMB);
  cudaFuncSetAttribute(attn_pb_kernel,
                       cudaFuncAttributeMaxDynamicSharedMemorySize, B_SMB);
  dim3 grid(S_DIM / QT, 32);
  rowsum_kernel<<<grid, NTHR, A_SMB>>>(q, k);
  attn_pb_kernel<<<grid, NTHR, B_SMB>>>(q, k, v, out);
}

// round 9
// speedup vs baseline: 1.7136x; 1.0602x over previous
#include <cuda_runtime.h>
#include <cstdint>

#define S_DIM 2048
#define QT 16
#define KT 64
#define NTHR 256
#define KBS 68             // K/V tile row stride (words)
#define OUT_O_ELEMS 4194304ull
#define KV_ELEMS 4194304   // B*H*S*D

__device__ float g_inv[65536];      // 1/rowsum per (bh,row)
__device__ float g_kt[KV_ELEMS];    // K pre-rounded to tf32
__device__ float g_vt[KV_ELEMS];    // V pre-rounded to tf32

__device__ __forceinline__ uint32_t smem_u32(const void* p) {
  uint32_t a;
  asm("{ .reg .u64 t; cvta.to.shared.u64 t, %1; cvt.u32.u64 %0, t; }" : "=r"(a) : "l"(p));
  return a;
}
__device__ __forceinline__ float tf32f(float x) {
  uint32_t u; asm("cvt.rna.tf32.f32 %0, %1;" : "=r"(u) : "f"(x));
  return __uint_as_float(u);
}
__device__ __forceinline__ void mma8(float c[4], const uint32_t a[4],
                                     uint32_t b0, uint32_t b1) {
  asm volatile("mma.sync.aligned.m16n8k8.row.col.f32.tf32.tf32.f32 "
    "{%0,%1,%2,%3}, {%4,%5,%6,%7}, {%8,%9}, {%0,%1,%2,%3};"
    : "+f"(c[0]), "+f"(c[1]), "+f"(c[2]), "+f"(c[3])
    : "r"(a[0]), "r"(a[1]), "r"(a[2]), "r"(a[3]), "r"(b0), "r"(b1));
}
#define CP16(dst, src) asm volatile("cp.async.ca.shared.global [%0], [%1], 16;" :: "r"(dst), "l"(src) : "memory")
#define CP_COMMIT()    asm volatile("cp.async.commit_group;" ::: "memory")
#define CP_WAIT0()     asm volatile("cp.async.wait_group 0;" ::: "memory")

// =================== PREP : round K,V to tf32 once ===================
__global__ void __launch_bounds__(256)
kv_round_kernel(const float* __restrict__ K, const float* __restrict__ V) {
  const int i = blockIdx.x * 256 + threadIdx.x;   // float4 index
  float4 k = ((const float4*)K)[i];
  k.x = tf32f(k.x); k.y = tf32f(k.y); k.z = tf32f(k.z); k.w = tf32f(k.w);
  ((float4*)g_kt)[i] = k;
  float4 v = ((const float4*)V)[i];
  v.x = tf32f(v.x); v.y = tf32f(v.y); v.z = tf32f(v.z); v.w = tf32f(v.w);
  ((float4*)g_vt)[i] = v;
}

// ======================= PASS A : row sums =======================
#define A_QSW 0
#define A_KBW 1088                      // 2*64*68 = 8704 w
#define A_REDW (A_KBW + 2 * KT * KBS)   // 9792
#define A_SMB ((A_REDW + 128) * 4)      // 39680 B

__global__ void __launch_bounds__(NTHR, 3)
rowsum_kernel(const float* __restrict__ Q) {
  extern __shared__ __align__(16) float smf[];
  const uint32_t sb = smem_u32(smf);
  const int tid = threadIdx.x;
  const int w = tid >> 5, lane = tid & 31;
  const int gid = lane >> 2, tg = lane & 3;
  const int bh = blockIdx.y;
  const int qt = (int)gridDim.x - 1 - (int)blockIdx.x;
  const int q0 = qt * QT;

  const float* Qg = Q + ((size_t)bh * S_DIM + q0) * 64;
  const float* Kg = g_kt + (size_t)bh * S_DIM * 64;

  { // stage Q (x 1/8, rna-tf32)
    int r = tid >> 4, f = tid & 15;
    float4 v = ((const float4*)Qg)[tid];
    float* d = &smf[A_QSW + r * KBS + 4 * f];
    d[0] = tf32f(v.x * 0.125f); d[1] = tf32f(v.y * 0.125f);
    d[2] = tf32f(v.z * 0.125f); d[3] = tf32f(v.w * 0.125f);
  }
  { // prolog: K tile 0 (already tf32-rounded)
    const char* kg0 = (const char*)Kg;
    #pragma unroll
    for (int it = 0; it < 4; ++it) {
      int idx = tid + it * NTHR;
      int r = idx >> 4, c = idx & 15;
      CP16(sb + (A_KBW + r * KBS) * 4 + c * 16, kg0 + r * 256 + c * 16);
    }
    CP_COMMIT();
  }
  __syncthreads();

  uint32_t af[8][4];
  #pragma unroll
  for (int s = 0; s < 8; ++s) {
    af[s][0] = __float_as_uint(smf[A_QSW + gid * KBS + s * 8 + tg]);
    af[s][1] = __float_as_uint(smf[A_QSW + (gid + 8) * KBS + s * 8 + tg]);
    af[s][2] = __float_as_uint(smf[A_QSW + gid * KBS + s * 8 + tg + 4]);
    af[s][3] = __float_as_uint(smf[A_QSW + (gid + 8) * KBS + s * 8 + tg + 4]);
  }

  const int nkt = (q0 + QT + KT - 1) >> 6;
  const int r0 = q0 + gid, r1 = r0 + 8;
  float rs0 = 0.f, rs1 = 0.f;

  for (int tt = 0; tt < nkt; ++tt) {
    const int kc = tt << 6;
    CP_WAIT0();
    __syncthreads();
    if (tt + 1 < nkt) {
      const char* kg1 = (const char*)(Kg + (size_t)(kc + KT) * 64);
      uint32_t dstb = sb + (A_KBW + ((tt + 1) & 1) * KT * KBS) * 4;
      #pragma unroll
      for (int it = 0; it < 4; ++it) {
        int idx = tid + it * NTHR;
        int r = idx >> 4, c = idx & 15;
        CP16(dstb + r * KBS * 4 + c * 16, kg1 + r * 256 + c * 16);
      }
      CP_COMMIT();
    }
    const float* kb = &smf[A_KBW + (tt & 1) * KT * KBS];

    float acca[4] = {0.f, 0.f, 0.f, 0.f};
    float accb[4] = {0.f, 0.f, 0.f, 0.f};
    const int ncol = w * 8 + gid;
    #pragma unroll
    for (int s = 0; s < 4; ++s) {
      uint32_t b0 = __float_as_uint(kb[ncol * KBS + s * 8 + tg]);
      uint32_t b1 = __float_as_uint(kb[ncol * KBS + s * 8 + tg + 4]);
      mma8(acca, af[s], b0, b1);
      uint32_t c0 = __float_as_uint(kb[ncol * KBS + (s + 4) * 8 + tg]);
      uint32_t c1 = __float_as_uint(kb[ncol * KBS + (s + 4) * 8 + tg + 4]);
      mma8(accb, af[s + 4], c0, c1);
    }
    const int cg = kc + w * 8 + 2 * tg;
    rs0 += ((cg     <= r0) ? __expf(acca[0] + accb[0]) : 0.f)
         + ((cg + 1 <= r0) ? __expf(acca[1] + accb[1]) : 0.f);
    rs1 += ((cg     <= r1) ? __expf(acca[2] + accb[2]) : 0.f)
         + ((cg + 1 <= r1) ? __expf(acca[3] + accb[3]) : 0.f);
  }

  rs0 += __shfl_xor_sync(~0u, rs0, 1); rs0 += __shfl_xor_sync(~0u, rs0, 2);
  rs1 += __shfl_xor_sync(~0u, rs1, 1); rs1 += __shfl_xor_sync(~0u, rs1, 2);
  if (tg == 0) { smf[A_REDW + w * 16 + gid] = rs0; smf[A_REDW + w * 16 + gid + 8] = rs1; }
  __syncthreads();
  if (tid < 16) {
    float s = 0.f;
    #pragma unroll
    for (int i = 0; i < 8; ++i) s += smf[A_REDW + i * 16 + tid];
    g_inv[bh * S_DIM + q0 + tid] = 1.0f / s;
  }
}

// ======================= PASS B : W + O =======================
#define B_QSW 0
#define B_KBW 1088
#define B_VBW (B_KBW + 2 * KT * KBS)    // 9792
#define B_SMB ((B_VBW + 2 * KT * KBS) * 4)  // 73984 B

__global__ void __launch_bounds__(NTHR, 2)
attn_pb_kernel(const float* __restrict__ Q, float* __restrict__ out) {
  extern __shared__ __align__(16) float smf[];
  const uint32_t sb = smem_u32(smf);
  const int tid = threadIdx.x;
  const int w = tid >> 5, lane = tid & 31;
  const int gid = lane >> 2, tg = lane & 3;
  const int bh = blockIdx.y;
  const int qt = (int)gridDim.x - 1 - (int)blockIdx.x;
  const int q0 = qt * QT;

  const float* Qg = Q + ((size_t)bh * S_DIM + q0) * 64;
  const float* Kg = g_kt + (size_t)bh * S_DIM * 64;
  const float* Vg = g_vt + (size_t)bh * S_DIM * 64;
  float* Og = out + ((size_t)bh * S_DIM + q0) * 64;
  float* Wg = out + OUT_O_ELEMS + ((size_t)bh * S_DIM + q0) * (size_t)S_DIM;

  const float iv0 = g_inv[bh * S_DIM + q0 + gid];
  const float iv1 = g_inv[bh * S_DIM + q0 + gid + 8];

  { // stage Q
    int r = tid >> 4, f = tid & 15;
    float4 v = ((const float4*)Qg)[tid];
    float* d = &smf[B_QSW + r * KBS + 4 * f];
    d[0] = tf32f(v.x * 0.125f); d[1] = tf32f(v.y * 0.125f);
    d[2] = tf32f(v.z * 0.125f); d[3] = tf32f(v.w * 0.125f);
  }
  { // prolog: K+V tile 0.  V chunk swizzle: word col (4c + 4r) & 63
    const char* kg0 = (const char*)Kg;
    const char* vg0 = (const char*)Vg;
    #pragma unroll
    for (int it = 0; it < 4; ++it) {
      int idx = tid + it * NTHR;
      int r = idx >> 4, c = idx & 15;
      CP16(sb + (B_KBW + r * KBS) * 4 + c * 16, kg0 + r * 256 + c * 16);
      CP16(sb + (B_VBW + r * KBS + (((c << 2) + (r << 2)) & 63)) * 4, vg0 + r * 256 + c * 16);
    }
    CP_COMMIT();
  }
  __syncthreads();

  uint32_t af[8][4];
  #pragma unroll
  for (int s = 0; s < 8; ++s) {
    af[s][0] = __float_as_uint(smf[B_QSW + gid * KBS + s * 8 + tg]);
    af[s][1] = __float_as_uint(smf[B_QSW + (gid + 8) * KBS + s * 8 + tg]);
    af[s][2] = __float_as_uint(smf[B_QSW + gid * KBS + s * 8 + tg + 4]);
    af[s][3] = __float_as_uint(smf[B_QSW + (gid + 8) * KBS + s * 8 + tg + 4]);
  }

  const int nkt = (q0 + QT + KT - 1) >> 6;
  const int r0 = q0 + gid, r1 = r0 + 8;
  float oc[8][4];
  #pragma unroll
  for (int j = 0; j < 8; ++j)
    #pragma unroll
    for (int u = 0; u < 4; ++u) oc[j][u] = 0.f;

  for (int tt = 0; tt < nkt; ++tt) {
    const int kc = tt << 6;
    CP_WAIT0();
    __syncthreads();
    if (tt + 1 < nkt) {
      const char* kg1 = (const char*)(Kg + (size_t)(kc + KT) * 64);
      const char* vg1 = (const char*)(Vg + (size_t)(kc + KT) * 64);
      uint32_t kd = sb + (B_KBW + ((tt + 1) & 1) * KT * KBS) * 4;
      uint32_t vd = sb + (B_VBW + ((tt + 1) & 1) * KT * KBS) * 4;
      #pragma unroll
      for (int it = 0; it < 4; ++it) {
        int idx = tid + it * NTHR;
        int r = idx >> 4, c = idx & 15;
        CP16(kd + r * KBS * 4 + c * 16, kg1 + r * 256 + c * 16);
        CP16(vd + (r * KBS + (((c << 2) + (r << 2)) & 63)) * 4, vg1 + r * 256 + c * 16);
      }
      CP_COMMIT();
    }
    const float* kb = &smf[B_KBW + (tt & 1) * KT * KBS];
    const float* vb = &smf[B_VBW + (tt & 1) * KT * KBS];

    // ---- QK: warp's n8 strip, two independent 4-MMA chains, no cvts ----
    float acca[4] = {0.f, 0.f, 0.f, 0.f};
    float accb[4] = {0.f, 0.f, 0.f, 0.f};
    const int ncol = w * 8 + gid;
    #pragma unroll
    for (int s = 0; s < 4; ++s) {
      uint32_t b0 = __float_as_uint(kb[ncol * KBS + s * 8 + tg]);
      uint32_t b1 = __float_as_uint(kb[ncol * KBS + s * 8 + tg + 4]);
      mma8(acca, af[s], b0, b1);
      uint32_t c0 = __float_as_uint(kb[ncol * KBS + (s + 4) * 8 + tg]);
      uint32_t c1 = __float_as_uint(kb[ncol * KBS + (s + 4) * 8 + tg + 4]);
      mma8(accb, af[s + 4], c0, c1);
    }

    // ---- final p = mask ? exp(s)*inv : 0 ; write W straight from regs ----
    const int cg = kc + w * 8 + 2 * tg;
    float e00 = (cg     <= r0) ? __expf(acca[0] + accb[0]) * iv0 : 0.f;
    float e01 = (cg + 1 <= r0) ? __expf(acca[1] + accb[1]) * iv0 : 0.f;
    float e10 = (cg     <= r1) ? __expf(acca[2] + accb[2]) * iv1 : 0.f;
    float e11 = (cg + 1 <= r1) ? __expf(acca[3] + accb[3]) * iv1 : 0.f;
    *(float2*)&Wg[(size_t)gid * S_DIM + cg]       = make_float2(e00, e01);
    *(float2*)&Wg[(size_t)(gid + 8) * S_DIM + cg] = make_float2(e10, e11);

    // ---- rebuild PV A-fragment via shuffles ----
    const int srcA = gid * 4 + (tg >> 1);
    const int srcB = srcA + 2;
    float a0 = __shfl_sync(~0u, e00, srcA), a1 = __shfl_sync(~0u, e01, srcA);
    float g0 = __shfl_sync(~0u, e10, srcA), g1 = __shfl_sync(~0u, e11, srcA);
    float h0 = __shfl_sync(~0u, e00, srcB), h1 = __shfl_sync(~0u, e01, srcB);
    float k0 = __shfl_sync(~0u, e10, srcB), k1 = __shfl_sync(~0u, e11, srcB);
    const bool odd = tg & 1;
    uint32_t pa[4];
    pa[0] = __float_as_uint(tf32f(odd ? a1 : a0));
    pa[1] = __float_as_uint(tf32f(odd ? g1 : g0));
    pa[2] = __float_as_uint(tf32f(odd ? h1 : h0));
    pa[3] = __float_as_uint(tf32f(odd ? k1 : k0));

    // ---- PV: warp's k8 slice x all 64 d-cols, no cvts ----
    const int kla = w * 8 + tg;
    #pragma unroll
    for (int j = 0; j < 8; ++j) {
      const int dcol = j * 8 + gid;
      uint32_t b0 = __float_as_uint(vb[kla * KBS + ((dcol + 4 * kla) & 63)]);
      uint32_t b1 = __float_as_uint(vb[(kla + 4) * KBS + ((dcol + 4 * kla + 16) & 63)]);
      mma8(oc[j], pa, b0, b1);
    }
  }

  // ---- W zero tail ----
  {
    const int ktend = nkt * KT;
    const int r = tid >> 4, f = tid & 15;
    float4* wrow = (float4*)(Wg + (size_t)r * S_DIM);
    const float4 z = make_float4(0.f, 0.f, 0.f, 0.f);
    for (int c4 = (ktend >> 2) + f; c4 < (S_DIM >> 2); c4 += 16) wrow[c4] = z;
  }

  // ---- O merge: 8 per-warp k-partials via smem reuse ----
  __syncthreads();
  {
    float* osc = &smf[w * (16 * 66)];
    #pragma unroll
    for (int j = 0; j < 8; ++j) {
      *(float2*)&osc[gid * 66 + j * 8 + 2 * tg]       = make_float2(oc[j][0], oc[j][1]);
      *(float2*)&osc[(gid + 8) * 66 + j * 8 + 2 * tg] = make_float2(oc[j][2], oc[j][3]);
    }
  }
  __syncthreads();
  #pragma unroll
  for (int it = 0; it < 4; ++it) {
    const int e = tid + it * NTHR;
    const int r = e >> 6, d = e & 63;
    float s = 0.f;
    #pragma unroll
    for (int p = 0; p < 8; ++p) s += smf[p * (16 * 66) + r * 66 + d];
    Og[r * 64 + d] = s;
  }
}

extern "C" void kernel_launch(void* const* d_in, const int* in_sizes, int n_in,
                              void* d_out, int out_size) {
  (void)in_sizes; (void)n_in; (void)out_size;
  const float* q = (const float*)d_in[0];
  const float* k = (const float*)d_in[1];
  const float* v = (const float*)d_in[2];
  float* out = (float*)d_out;

  cudaFuncSetAttribute(rowsum_kernel,
                       cudaFuncAttributeMaxDynamicSharedMemorySize, A_SMB);
  cudaFuncSetAttribute(attn_pb_kernel,
                       cudaFuncAttributeMaxDynamicSharedMemorySize, B_SMB);
  dim3 grid(S_DIM / QT, 32);
  kv_round_kernel<<<KV_ELEMS / 4 / 256, 256>>>(k, v);
  rowsum_kernel<<<grid, NTHR, A_SMB>>>(q);
  attn_pb_kernel<<<grid, NTHR, B_SMB>>>(q, out);
}

// round 10
// speedup vs baseline: 2.6847x; 1.5667x over previous
#include <cuda_runtime.h>
#include <cstdint>

#define S_DIM 2048
#define QT 16
#define KT 128
#define NTHR 256
#define OUT_O_ELEMS 4194304ull
#define KV_ELEMS 4194304

__device__ float    g_inv[65536];          // 1/rowsum per (bh,row)
__device__ uint32_t g_kh[KV_ELEMS / 2];    // K fp16 (half2 words along d)
__device__ uint32_t g_vh[KV_ELEMS / 2];    // V fp16, k-paired: word(k2,d)={V[2k2][d],V[2k2+1][d]}

__device__ __forceinline__ uint32_t smem_u32(const void* p) {
  uint32_t a;
  asm("{ .reg .u64 t; cvta.to.shared.u64 t, %1; cvt.u32.u64 %0, t; }" : "=r"(a) : "l"(p));
  return a;
}
__device__ __forceinline__ uint32_t packh2(float lo, float hi) {
  uint32_t r; asm("cvt.rn.f16x2.f32 %0, %1, %2;" : "=r"(r) : "f"(hi), "f"(lo));
  return r;
}
__device__ __forceinline__ void mma16(float c[4], const uint32_t a[4],
                                      uint32_t b0, uint32_t b1) {
  asm volatile("mma.sync.aligned.m16n8k16.row.col.f32.f16.f16.f32 "
    "{%0,%1,%2,%3}, {%4,%5,%6,%7}, {%8,%9}, {%0,%1,%2,%3};"
    : "+f"(c[0]), "+f"(c[1]), "+f"(c[2]), "+f"(c[3])
    : "r"(a[0]), "r"(a[1]), "r"(a[2]), "r"(a[3]), "r"(b0), "r"(b1));
}
#define CP16(dst, src) asm volatile("cp.async.ca.shared.global [%0], [%1], 16;" :: "r"(dst), "l"(src) : "memory")
#define CP_COMMIT()    asm volatile("cp.async.commit_group;" ::: "memory")
#define CP_WAIT0()     asm volatile("cp.async.wait_group 0;" ::: "memory")

// =================== PREP : K,V -> fp16 (V k-paired) ===================
__global__ void __launch_bounds__(256)
kv_prep_kernel(const float* __restrict__ K, const float* __restrict__ V) {
  const int i = blockIdx.x * 256 + threadIdx.x;        // 0..1048575
  float4 k = ((const float4*)K)[i];
  ((uint2*)g_kh)[i] = make_uint2(packh2(k.x, k.y), packh2(k.z, k.w));
  const int k2g = i >> 5, d2 = i & 31;                 // V: pair rows 2k2g,2k2g+1
  const float2* v0 = (const float2*)(V + (size_t)k2g * 128);
  float2 a = v0[d2], b = v0[32 + d2];
  ((uint2*)g_vh)[(size_t)k2g * 32 + d2] = make_uint2(packh2(a.x, b.x), packh2(a.y, b.y));
}

// ======================= PASS A : row sums =======================
// smem words: Q[576] K[2*4608]  red[144]
#define A_QW 0
#define A_KW 576
#define A_RW (A_KW + 9216)
#define A_SMB ((A_RW + 144) * 4)

__global__ void __launch_bounds__(NTHR, 4)
rowsum_kernel(const float* __restrict__ Q) {
  extern __shared__ __align__(16) uint32_t smw[];
  const uint32_t sb = smem_u32(smw);
  const int tid = threadIdx.x;
  const int w = tid >> 5, lane = tid & 31;
  const int gid = lane >> 2, tg = lane & 3;
  const int bh = blockIdx.y;
  const int qt = (int)gridDim.x - 1 - (int)blockIdx.x;
  const int q0 = qt * QT;

  const float* Qg = Q + ((size_t)bh * S_DIM + q0) * 64;
  const char* Kg = (const char*)g_kh + (size_t)bh * 262144;

  { // stage Q (x 1/8) as fp16
    int r = tid >> 4, f = tid & 15;
    float4 v = ((const float4*)Qg)[tid];
    ((uint2*)(smw + A_QW + r * 36 + 2 * f))[0] =
        make_uint2(packh2(v.x * 0.125f, v.y * 0.125f), packh2(v.z * 0.125f, v.w * 0.125f));
  }
  { // prolog: K tile 0
    #pragma unroll
    for (int it = 0; it < 4; ++it) {
      int idx = tid + it * NTHR;             // 1024 chunks
      int r = idx >> 3, c = idx & 7;
      CP16(sb + (A_KW * 4) + r * 144 + c * 16, Kg + r * 128 + c * 16);
    }
    CP_COMMIT();
  }
  __syncthreads();

  uint32_t af[4][4];
  #pragma unroll
  for (int s = 0; s < 4; ++s) {
    af[s][0] = smw[A_QW + gid * 36 + 8 * s + tg];
    af[s][1] = smw[A_QW + (gid + 8) * 36 + 8 * s + tg];
    af[s][2] = smw[A_QW + gid * 36 + 8 * s + 4 + tg];
    af[s][3] = smw[A_QW + (gid + 8) * 36 + 8 * s + 4 + tg];
  }

  const int nkt = (qt + 8) >> 3;
  const int r0 = q0 + gid, r1 = r0 + 8;
  float rs0 = 0.f, rs1 = 0.f;

  for (int tt = 0; tt < nkt; ++tt) {
    const int kc = tt << 7;
    CP_WAIT0();
    __syncthreads();
    if (tt + 1 < nkt) {
      const char* kg1 = Kg + (size_t)(kc + KT) * 128;
      uint32_t kd = sb + (A_KW + ((tt + 1) & 1) * 4608) * 4;
      #pragma unroll
      for (int it = 0; it < 4; ++it) {
        int idx = tid + it * NTHR;
        int r = idx >> 3, c = idx & 7;
        CP16(kd + r * 144 + c * 16, kg1 + r * 128 + c * 16);
      }
      CP_COMMIT();
    }
    const uint32_t* kb = smw + A_KW + (tt & 1) * 4608;

    float acc0[4] = {0.f, 0.f, 0.f, 0.f};
    float acc1[4] = {0.f, 0.f, 0.f, 0.f};
    const int nc0 = (16 * w + gid) * 36, nc1 = (16 * w + 8 + gid) * 36;
    #pragma unroll
    for (int s = 0; s < 4; ++s) {
      mma16(acc0, af[s], kb[nc0 + 8 * s + tg], kb[nc0 + 8 * s + 4 + tg]);
      mma16(acc1, af[s], kb[nc1 + 8 * s + tg], kb[nc1 + 8 * s + 4 + tg]);
    }
    const int cg0 = kc + 16 * w + 2 * tg, cg1 = cg0 + 8;
    rs0 += ((cg0     <= r0) ? __expf(acc0[0]) : 0.f)
         + ((cg0 + 1 <= r0) ? __expf(acc0[1]) : 0.f)
         + ((cg1     <= r0) ? __expf(acc1[0]) : 0.f)
         + ((cg1 + 1 <= r0) ? __expf(acc1[1]) : 0.f);
    rs1 += ((cg0     <= r1) ? __expf(acc0[2]) : 0.f)
         + ((cg0 + 1 <= r1) ? __expf(acc0[3]) : 0.f)
         + ((cg1     <= r1) ? __expf(acc1[2]) : 0.f)
         + ((cg1 + 1 <= r1) ? __expf(acc1[3]) : 0.f);
  }

  rs0 += __shfl_xor_sync(~0u, rs0, 1); rs0 += __shfl_xor_sync(~0u, rs0, 2);
  rs1 += __shfl_xor_sync(~0u, rs1, 1); rs1 += __shfl_xor_sync(~0u, rs1, 2);
  float* red = (float*)(smw + A_RW);
  if (tg == 0) { red[w * 16 + gid] = rs0; red[w * 16 + gid + 8] = rs1; }
  __syncthreads();
  if (tid < 16) {
    float s = 0.f;
    #pragma unroll
    for (int i = 0; i < 8; ++i) s += red[i * 16 + tid];
    g_inv[bh * S_DIM + q0 + tid] = 1.0f / s;
  }
}

// ======================= PASS B : W + O =======================
// smem words: Q[576] K[2*4608] V[2*4352]
#define B_QW 0
#define B_KW 576
#define B_VW (B_KW + 9216)          // 9792
#define B_SMB ((B_VW + 8704) * 4)   // 73984 B

__global__ void __launch_bounds__(NTHR, 2)
attn_pb_kernel(const float* __restrict__ Q, float* __restrict__ out) {
  extern __shared__ __align__(16) uint32_t smw[];
  const uint32_t sb = smem_u32(smw);
  const int tid = threadIdx.x;
  const int w = tid >> 5, lane = tid & 31;
  const int gid = lane >> 2, tg = lane & 3;
  const int bh = blockIdx.y;
  const int qt = (int)gridDim.x - 1 - (int)blockIdx.x;
  const int q0 = qt * QT;

  const float* Qg = Q + ((size_t)bh * S_DIM + q0) * 64;
  const char* Kg = (const char*)g_kh + (size_t)bh * 262144;
  const char* Vg = (const char*)g_vh + (size_t)bh * 262144;
  float* Og = out + ((size_t)bh * S_DIM + q0) * 64;
  float* Wg = out + OUT_O_ELEMS + ((size_t)bh * S_DIM + q0) * (size_t)S_DIM;

  const float iv0 = g_inv[bh * S_DIM + q0 + gid];
  const float iv1 = g_inv[bh * S_DIM + q0 + gid + 8];

  { // stage Q (x 1/8) as fp16
    int r = tid >> 4, f = tid & 15;
    float4 v = ((const float4*)Qg)[tid];
    ((uint2*)(smw + B_QW + r * 36 + 2 * f))[0] =
        make_uint2(packh2(v.x * 0.125f, v.y * 0.125f), packh2(v.z * 0.125f, v.w * 0.125f));
  }
  { // prolog: K + V tile 0
    #pragma unroll
    for (int it = 0; it < 4; ++it) {
      int idx = tid + it * NTHR;
      int r = idx >> 3, c = idx & 7;
      CP16(sb + B_KW * 4 + r * 144 + c * 16, Kg + r * 128 + c * 16);
    }
    #pragma unroll
    for (int it = 0; it < 4; ++it) {
      int idx = tid + it * NTHR;
      int k2 = idx >> 4, c = idx & 15;
      CP16(sb + B_VW * 4 + k2 * 272 + (((c << 2) + 4 * (k2 & 15)) & 63) * 4,
           Vg + k2 * 256 + c * 16);
    }
    CP_COMMIT();
  }
  __syncthreads();

  uint32_t af[4][4];
  #pragma unroll
  for (int s = 0; s < 4; ++s) {
    af[s][0] = smw[B_QW + gid * 36 + 8 * s + tg];
    af[s][1] = smw[B_QW + (gid + 8) * 36 + 8 * s + tg];
    af[s][2] = smw[B_QW + gid * 36 + 8 * s + 4 + tg];
    af[s][3] = smw[B_QW + (gid + 8) * 36 + 8 * s + 4 + tg];
  }

  const int nkt = (qt + 8) >> 3;
  const int r0 = q0 + gid, r1 = r0 + 8;
  float oc[8][4];
  #pragma unroll
  for (int j = 0; j < 8; ++j)
    #pragma unroll
    for (int u = 0; u < 4; ++u) oc[j][u] = 0.f;

  for (int tt = 0; tt < nkt; ++tt) {
    const int kc = tt << 7;
    CP_WAIT0();
    __syncthreads();
    if (tt + 1 < nkt) {
      const char* kg1 = Kg + (size_t)(kc + KT) * 128;
      const char* vg1 = Vg + (size_t)(kc >> 1) * 256 + 64 * 256;
      uint32_t kd = sb + (B_KW + ((tt + 1) & 1) * 4608) * 4;
      uint32_t vd = sb + (B_VW + ((tt + 1) & 1) * 4352) * 4;
      #pragma unroll
      for (int it = 0; it < 4; ++it) {
        int idx = tid + it * NTHR;
        int r = idx >> 3, c = idx & 7;
        CP16(kd + r * 144 + c * 16, kg1 + r * 128 + c * 16);
      }
      #pragma unroll
      for (int it = 0; it < 4; ++it) {
        int idx = tid + it * NTHR;
        int k2 = idx >> 4, c = idx & 15;
        CP16(vd + k2 * 272 + (((c << 2) + 4 * (k2 & 15)) & 63) * 4,
             vg1 + k2 * 256 + c * 16);
      }
      CP_COMMIT();
    }
    const uint32_t* kb = smw + B_KW + (tt & 1) * 4608;
    const uint32_t* vb = smw + B_VW + (tt & 1) * 4352;

    // ---- QK: warp's n16 strip, 2 independent 4-MMA chains ----
    float acc0[4] = {0.f, 0.f, 0.f, 0.f};
    float acc1[4] = {0.f, 0.f, 0.f, 0.f};
    const int nc0 = (16 * w + gid) * 36, nc1 = (16 * w + 8 + gid) * 36;
    #pragma unroll
    for (int s = 0; s < 4; ++s) {
      mma16(acc0, af[s], kb[nc0 + 8 * s + tg], kb[nc0 + 8 * s + 4 + tg]);
      mma16(acc1, af[s], kb[nc1 + 8 * s + tg], kb[nc1 + 8 * s + 4 + tg]);
    }

    // ---- p = mask ? exp(s)*inv : 0 ; write W straight from regs ----
    const int cg0 = kc + 16 * w + 2 * tg, cg1 = cg0 + 8;
    float e000 = (cg0     <= r0) ? __expf(acc0[0]) * iv0 : 0.f;
    float e001 = (cg0 + 1 <= r0) ? __expf(acc0[1]) * iv0 : 0.f;
    float e010 = (cg0     <= r1) ? __expf(acc0[2]) * iv1 : 0.f;
    float e011 = (cg0 + 1 <= r1) ? __expf(acc0[3]) * iv1 : 0.f;
    float e100 = (cg1     <= r0) ? __expf(acc1[0]) * iv0 : 0.f;
    float e101 = (cg1 + 1 <= r0) ? __expf(acc1[1]) * iv0 : 0.f;
    float e110 = (cg1     <= r1) ? __expf(acc1[2]) * iv1 : 0.f;
    float e111 = (cg1 + 1 <= r1) ? __expf(acc1[3]) * iv1 : 0.f;
    *(float2*)&Wg[(size_t)gid * S_DIM + cg0]       = make_float2(e000, e001);
    *(float2*)&Wg[(size_t)(gid + 8) * S_DIM + cg0] = make_float2(e010, e011);
    *(float2*)&Wg[(size_t)gid * S_DIM + cg1]       = make_float2(e100, e101);
    *(float2*)&Wg[(size_t)(gid + 8) * S_DIM + cg1] = make_float2(e110, e111);

    // ---- PV A-fragment: direct register pack, no shuffles ----
    uint32_t pa[4];
    pa[0] = packh2(e000, e001);
    pa[1] = packh2(e010, e011);
    pa[2] = packh2(e100, e101);
    pa[3] = packh2(e110, e111);

    // ---- PV: warp's k16 slice x all 64 d-cols (paired V, swizzled) ----
    const int k2a = 8 * w + tg, k2b = k2a + 4;
    const int swa = 4 * (k2a & 15), swb = 4 * (k2b & 15);
    #pragma unroll
    for (int j = 0; j < 8; ++j) {
      const int d = 8 * j + gid;
      uint32_t b0 = vb[k2a * 68 + ((d + swa) & 63)];
      uint32_t b1 = vb[k2b * 68 + ((d + swb) & 63)];
      mma16(oc[j], pa, b0, b1);
    }
  }

  // ---- W zero tail ----
  {
    const int ktend = nkt * KT;
    const int r = tid >> 4, f = tid & 15;
    float4* wrow = (float4*)(Wg + (size_t)r * S_DIM);
    const float4 z = make_float4(0.f, 0.f, 0.f, 0.f);
    for (int c4 = (ktend >> 2) + f; c4 < (S_DIM >> 2); c4 += 16) wrow[c4] = z;
  }

  // ---- O merge: 8 per-warp k-partials via smem reuse ----
  __syncthreads();
  float* smf = (float*)smw;
  {
    float* osc = &smf[w * (16 * 66)];
    #pragma unroll
    for (int j = 0; j < 8; ++j) {
      *(float2*)&osc[gid * 66 + j * 8 + 2 * tg]       = make_float2(oc[j][0], oc[j][1]);
      *(float2*)&osc[(gid + 8) * 66 + j * 8 + 2 * tg] = make_float2(oc[j][2], oc[j][3]);
    }
  }
  __syncthreads();
  #pragma unroll
  for (int it = 0; it < 4; ++it) {
    const int e = tid + it * NTHR;
    const int r = e >> 6, d = e & 63;
    float s = 0.f;
    #pragma unroll
    for (int p = 0; p < 8; ++p) s += smf[p * (16 * 66) + r * 66 + d];
    Og[r * 64 + d] = s;
  }
}

extern "C" void kernel_launch(void* const* d_in, const int* in_sizes, int n_in,
                              void* d_out, int out_size) {
  (void)in_sizes; (void)n_in; (void)out_size;
  const float* q = (const float*)d_in[0];
  const float* k = (const float*)d_in[1];
  const float* v = (const float*)d_in[2];
  float* out = (float*)d_out;

  cudaFuncSetAttribute(rowsum_kernel,
                       cudaFuncAttributeMaxDynamicSharedMemorySize, A_SMB);
  cudaFuncSetAttribute(attn_pb_kernel,
                       cudaFuncAttributeMaxDynamicSharedMemorySize, B_SMB);
  dim3 grid(S_DIM / QT, 32);
  kv_prep_kernel<<<KV_ELEMS / 4 / 256, 256>>>(k, v);
  rowsum_kernel<<<grid, NTHR, A_SMB>>>(q);
  attn_pb_kernel<<<grid, NTHR, B_SMB>>>(q, out);
}

// round 11
// speedup vs baseline: 3.0141x; 1.1227x over previous
#include <cuda_runtime.h>
#include <cstdint>

#define S_DIM 2048
#define QT 32
#define KT 128
#define NTHR 256
#define OUT_O_ELEMS 4194304ull
#define KV_ELEMS 4194304

__device__ float    g_inv[65536];          // 1/rowsum per (bh,row)
__device__ uint32_t g_kh[KV_ELEMS / 2];    // K fp16 (half2 words along d)
__device__ uint32_t g_vh[KV_ELEMS / 2];    // V fp16, k-paired: word(k2,d)={V[2k2][d],V[2k2+1][d]}

__device__ __forceinline__ uint32_t smem_u32(const void* p) {
  uint32_t a;
  asm("{ .reg .u64 t; cvta.to.shared.u64 t, %1; cvt.u32.u64 %0, t; }" : "=r"(a) : "l"(p));
  return a;
}
__device__ __forceinline__ uint32_t packh2(float lo, float hi) {
  uint32_t r; asm("cvt.rn.f16x2.f32 %0, %1, %2;" : "=r"(r) : "f"(hi), "f"(lo));
  return r;
}
__device__ __forceinline__ void mma16(float c[4], const uint32_t a[4],
                                      uint32_t b0, uint32_t b1) {
  asm volatile("mma.sync.aligned.m16n8k16.row.col.f32.f16.f16.f32 "
    "{%0,%1,%2,%3}, {%4,%5,%6,%7}, {%8,%9}, {%0,%1,%2,%3};"
    : "+f"(c[0]), "+f"(c[1]), "+f"(c[2]), "+f"(c[3])
    : "r"(a[0]), "r"(a[1]), "r"(a[2]), "r"(a[3]), "r"(b0), "r"(b1));
}
#define CP16(dst, src) asm volatile("cp.async.ca.shared.global [%0], [%1], 16;" :: "r"(dst), "l"(src) : "memory")
#define CP_COMMIT()    asm volatile("cp.async.commit_group;" ::: "memory")
#define CP_WAIT0()     asm volatile("cp.async.wait_group 0;" ::: "memory")

// =================== PREP : K,V -> fp16 (V k-paired) ===================
__global__ void __launch_bounds__(256)
kv_prep_kernel(const float* __restrict__ K, const float* __restrict__ V) {
  const int i = blockIdx.x * 256 + threadIdx.x;
  float4 k = ((const float4*)K)[i];
  ((uint2*)g_kh)[i] = make_uint2(packh2(k.x, k.y), packh2(k.z, k.w));
  const int k2g = i >> 5, d2 = i & 31;
  const float2* v0 = (const float2*)(V + (size_t)k2g * 128);
  float2 a = v0[d2], b = v0[32 + d2];
  ((uint2*)g_vh)[(size_t)k2g * 32 + d2] = make_uint2(packh2(a.x, b.x), packh2(a.y, b.y));
}

// ======================= PASS A : row sums (QT=32) =======================
// smem words: Q[32*36=1152] K[2*4608] red[256]
#define A_QW 0
#define A_KW 1152
#define A_RW (A_KW + 9216)
#define A_SMB ((A_RW + 256) * 4)    // 42496 B

__global__ void __launch_bounds__(NTHR, 3)
rowsum_kernel(const float* __restrict__ Q) {
  extern __shared__ __align__(16) uint32_t smw[];
  const uint32_t sb = smem_u32(smw);
  const int tid = threadIdx.x;
  const int w = tid >> 5, lane = tid & 31;
  const int gid = lane >> 2, tg = lane & 3;
  const int bh = blockIdx.y;
  const int qt = (int)gridDim.x - 1 - (int)blockIdx.x;
  const int q0 = qt * QT;

  const float* Qg = Q + ((size_t)bh * S_DIM + q0) * 64;
  const char* Kg = (const char*)g_kh + (size_t)bh * 262144;

  { // stage Q (x 1/8) as fp16: 32 rows x 16 float4
    #pragma unroll
    for (int it = 0; it < 2; ++it) {
      int idx = tid + it * NTHR;
      int r = idx >> 4, f = idx & 15;
      float4 v = ((const float4*)Qg)[idx];
      ((uint2*)(smw + A_QW + r * 36 + 2 * f))[0] =
          make_uint2(packh2(v.x * 0.125f, v.y * 0.125f), packh2(v.z * 0.125f, v.w * 0.125f));
    }
  }
  { // prolog: K tile 0
    #pragma unroll
    for (int it = 0; it < 4; ++it) {
      int idx = tid + it * NTHR;
      int r = idx >> 3, c = idx & 7;
      CP16(sb + A_KW * 4 + r * 144 + c * 16, Kg + r * 128 + c * 16);
    }
    CP_COMMIT();
  }
  __syncthreads();

  uint32_t af[2][4][4];
  #pragma unroll
  for (int a = 0; a < 2; ++a)
    #pragma unroll
    for (int s = 0; s < 4; ++s) {
      af[a][s][0] = smw[A_QW + (gid + 16 * a) * 36 + 8 * s + tg];
      af[a][s][1] = smw[A_QW + (gid + 8 + 16 * a) * 36 + 8 * s + tg];
      af[a][s][2] = smw[A_QW + (gid + 16 * a) * 36 + 8 * s + 4 + tg];
      af[a][s][3] = smw[A_QW + (gid + 8 + 16 * a) * 36 + 8 * s + 4 + tg];
    }

  const int nkt = (q0 + QT + 127) >> 7;
  float rs[4] = {0.f, 0.f, 0.f, 0.f};

  for (int tt = 0; tt < nkt; ++tt) {
    const int kc = tt << 7;
    CP_WAIT0();
    __syncthreads();
    if (tt + 1 < nkt) {
      const char* kg1 = Kg + (size_t)(kc + KT) * 128;
      uint32_t kd = sb + (A_KW + ((tt + 1) & 1) * 4608) * 4;
      #pragma unroll
      for (int it = 0; it < 4; ++it) {
        int idx = tid + it * NTHR;
        int r = idx >> 3, c = idx & 7;
        CP16(kd + r * 144 + c * 16, kg1 + r * 128 + c * 16);
      }
      CP_COMMIT();
    }
    const uint32_t* kb = smw + A_KW + (tt & 1) * 4608;
    const int nc0 = (16 * w + gid) * 36, nc1 = (16 * w + 8 + gid) * 36;
    const int cg0 = kc + 16 * w + 2 * tg, cg1 = cg0 + 8;

    #pragma unroll
    for (int a = 0; a < 2; ++a) {
      float acc0[4] = {0.f, 0.f, 0.f, 0.f};
      float acc1[4] = {0.f, 0.f, 0.f, 0.f};
      #pragma unroll
      for (int s = 0; s < 4; ++s) {
        mma16(acc0, af[a][s], kb[nc0 + 8 * s + tg], kb[nc0 + 8 * s + 4 + tg]);
        mma16(acc1, af[a][s], kb[nc1 + 8 * s + tg], kb[nc1 + 8 * s + 4 + tg]);
      }
      const int ra = q0 + gid + 16 * a, rb = ra + 8;
      rs[2 * a] += ((cg0     <= ra) ? __expf(acc0[0]) : 0.f)
                 + ((cg0 + 1 <= ra) ? __expf(acc0[1]) : 0.f)
                 + ((cg1     <= ra) ? __expf(acc1[0]) : 0.f)
                 + ((cg1 + 1 <= ra) ? __expf(acc1[1]) : 0.f);
      rs[2 * a + 1] += ((cg0     <= rb) ? __expf(acc0[2]) : 0.f)
                     + ((cg0 + 1 <= rb) ? __expf(acc0[3]) : 0.f)
                     + ((cg1     <= rb) ? __expf(acc1[2]) : 0.f)
                     + ((cg1 + 1 <= rb) ? __expf(acc1[3]) : 0.f);
    }
  }

  #pragma unroll
  for (int u = 0; u < 4; ++u) {
    rs[u] += __shfl_xor_sync(~0u, rs[u], 1);
    rs[u] += __shfl_xor_sync(~0u, rs[u], 2);
  }
  float* red = (float*)(smw + A_RW);
  if (tg == 0) {
    red[w * 32 + gid]      = rs[0];
    red[w * 32 + gid + 8]  = rs[1];
    red[w * 32 + gid + 16] = rs[2];
    red[w * 32 + gid + 24] = rs[3];
  }
  __syncthreads();
  if (tid < 32) {
    float s = 0.f;
    #pragma unroll
    for (int i = 0; i < 8; ++i) s += red[i * 32 + tid];
    g_inv[bh * S_DIM + q0 + tid] = 1.0f / s;
  }
}

// ======================= PASS B : W + O (QT=32) =======================
// smem words: Q[1152] K[2*4608] V[2*4352] P[32*68=2176]
#define B_QW 0
#define B_KW 1152
#define B_VW (B_KW + 9216)           // 10368
#define B_PW (B_VW + 8704)           // 19072
#define B_SMB ((B_PW + 2176) * 4)    // 84992 B

__global__ void __launch_bounds__(NTHR, 2)
attn_pb_kernel(const float* __restrict__ Q, float* __restrict__ out) {
  extern __shared__ __align__(16) uint32_t smw[];
  const uint32_t sb = smem_u32(smw);
  const int tid = threadIdx.x;
  const int w = tid >> 5, lane = tid & 31;
  const int gid = lane >> 2, tg = lane & 3;
  const int bh = blockIdx.y;
  const int qt = (int)gridDim.x - 1 - (int)blockIdx.x;
  const int q0 = qt * QT;

  const float* Qg = Q + ((size_t)bh * S_DIM + q0) * 64;
  const char* Kg = (const char*)g_kh + (size_t)bh * 262144;
  const char* Vg = (const char*)g_vh + (size_t)bh * 262144;
  float* Og = out + ((size_t)bh * S_DIM + q0) * 64;
  float* Wg = out + OUT_O_ELEMS + ((size_t)bh * S_DIM + q0) * (size_t)S_DIM;

  const float iv0 = g_inv[bh * S_DIM + q0 + gid];
  const float iv1 = g_inv[bh * S_DIM + q0 + gid + 8];
  const float iv2 = g_inv[bh * S_DIM + q0 + gid + 16];
  const float iv3 = g_inv[bh * S_DIM + q0 + gid + 24];

  { // stage Q (x 1/8) as fp16
    #pragma unroll
    for (int it = 0; it < 2; ++it) {
      int idx = tid + it * NTHR;
      int r = idx >> 4, f = idx & 15;
      float4 v = ((const float4*)Qg)[idx];
      ((uint2*)(smw + B_QW + r * 36 + 2 * f))[0] =
          make_uint2(packh2(v.x * 0.125f, v.y * 0.125f), packh2(v.z * 0.125f, v.w * 0.125f));
    }
  }
  { // prolog: K + V tile 0
    #pragma unroll
    for (int it = 0; it < 4; ++it) {
      int idx = tid + it * NTHR;
      int r = idx >> 3, c = idx & 7;
      CP16(sb + B_KW * 4 + r * 144 + c * 16, Kg + r * 128 + c * 16);
    }
    #pragma unroll
    for (int it = 0; it < 4; ++it) {
      int idx = tid + it * NTHR;
      int k2 = idx >> 4, c = idx & 15;
      CP16(sb + B_VW * 4 + k2 * 272 + (((c << 2) + 4 * (k2 & 15)) & 63) * 4,
           Vg + k2 * 256 + c * 16);
    }
    CP_COMMIT();
  }
  __syncthreads();

  uint32_t af[2][4][4];
  #pragma unroll
  for (int a = 0; a < 2; ++a)
    #pragma unroll
    for (int s = 0; s < 4; ++s) {
      af[a][s][0] = smw[B_QW + (gid + 16 * a) * 36 + 8 * s + tg];
      af[a][s][1] = smw[B_QW + (gid + 8 + 16 * a) * 36 + 8 * s + tg];
      af[a][s][2] = smw[B_QW + (gid + 16 * a) * 36 + 8 * s + 4 + tg];
      af[a][s][3] = smw[B_QW + (gid + 8 + 16 * a) * 36 + 8 * s + 4 + tg];
    }

  const int nkt = (q0 + QT + 127) >> 7;
  float oc[8][4];
  #pragma unroll
  for (int j = 0; j < 8; ++j)
    #pragma unroll
    for (int u = 0; u < 4; ++u) oc[j][u] = 0.f;

  // PV role: warp = (atom a2, k32-slice s2)
  const int a2 = w >> 2, s2 = w & 3;
  uint32_t* pw = smw + B_PW;

  for (int tt = 0; tt < nkt; ++tt) {
    const int kc = tt << 7;
    CP_WAIT0();
    __syncthreads();
    if (tt + 1 < nkt) {
      const char* kg1 = Kg + (size_t)(kc + KT) * 128;
      const char* vg1 = Vg + (size_t)(kc >> 1) * 256 + 64 * 256;
      uint32_t kd = sb + (B_KW + ((tt + 1) & 1) * 4608) * 4;
      uint32_t vd = sb + (B_VW + ((tt + 1) & 1) * 4352) * 4;
      #pragma unroll
      for (int it = 0; it < 4; ++it) {
        int idx = tid + it * NTHR;
        int r = idx >> 3, c = idx & 7;
        CP16(kd + r * 144 + c * 16, kg1 + r * 128 + c * 16);
      }
      #pragma unroll
      for (int it = 0; it < 4; ++it) {
        int idx = tid + it * NTHR;
        int k2 = idx >> 4, c = idx & 15;
        CP16(vd + k2 * 272 + (((c << 2) + 4 * (k2 & 15)) & 63) * 4,
             vg1 + k2 * 256 + c * 16);
      }
      CP_COMMIT();
    }
    const uint32_t* kb = smw + B_KW + (tt & 1) * 4608;
    const uint32_t* vb = smw + B_VW + (tt & 1) * 4352;

    // ---- QK both atoms on warp's n16 strip; W + p(smem) from regs ----
    const int nc0 = (16 * w + gid) * 36, nc1 = (16 * w + 8 + gid) * 36;
    const int cg0 = kc + 16 * w + 2 * tg, cg1 = cg0 + 8;
    const int k2w0 = 8 * w + tg, k2w1 = 8 * w + 4 + tg;
    #pragma unroll
    for (int a = 0; a < 2; ++a) {
      float acc0[4] = {0.f, 0.f, 0.f, 0.f};
      float acc1[4] = {0.f, 0.f, 0.f, 0.f};
      #pragma unroll
      for (int s = 0; s < 4; ++s) {
        mma16(acc0, af[a][s], kb[nc0 + 8 * s + tg], kb[nc0 + 8 * s + 4 + tg]);
        mma16(acc1, af[a][s], kb[nc1 + 8 * s + tg], kb[nc1 + 8 * s + 4 + tg]);
      }
      const int ra = q0 + gid + 16 * a, rb = ra + 8;
      const float iva = a ? iv2 : iv0, ivb = a ? iv3 : iv1;
      float e000 = (cg0     <= ra) ? __expf(acc0[0]) * iva : 0.f;
      float e001 = (cg0 + 1 <= ra) ? __expf(acc0[1]) * iva : 0.f;
      float e010 = (cg0     <= rb) ? __expf(acc0[2]) * ivb : 0.f;
      float e011 = (cg0 + 1 <= rb) ? __expf(acc0[3]) * ivb : 0.f;
      float e100 = (cg1     <= ra) ? __expf(acc1[0]) * iva : 0.f;
      float e101 = (cg1 + 1 <= ra) ? __expf(acc1[1]) * iva : 0.f;
      float e110 = (cg1     <= rb) ? __expf(acc1[2]) * ivb : 0.f;
      float e111 = (cg1 + 1 <= rb) ? __expf(acc1[3]) * ivb : 0.f;
      const int rla = gid + 16 * a, rlb = rla + 8;
      *(float2*)&Wg[(size_t)rla * S_DIM + cg0] = make_float2(e000, e001);
      *(float2*)&Wg[(size_t)rlb * S_DIM + cg0] = make_float2(e010, e011);
      *(float2*)&Wg[(size_t)rla * S_DIM + cg1] = make_float2(e100, e101);
      *(float2*)&Wg[(size_t)rlb * S_DIM + cg1] = make_float2(e110, e111);
      pw[rla * 68 + k2w0] = packh2(e000, e001);
      pw[rlb * 68 + k2w0] = packh2(e010, e011);
      pw[rla * 68 + k2w1] = packh2(e100, e101);
      pw[rlb * 68 + k2w1] = packh2(e110, e111);
    }
    __syncthreads();   // p tile complete before cross-warp PV reads

    // ---- PV: warp (a2, s2): rows of atom a2, k32 slice s2, all 64 d ----
    const int rpa = (gid + 16 * a2) * 68, rpb = (gid + 8 + 16 * a2) * 68;
    #pragma unroll
    for (int c = 0; c < 2; ++c) {
      const int base = 16 * s2 + 8 * c;
      uint32_t pa[4];
      pa[0] = pw[rpa + base + tg];
      pa[1] = pw[rpb + base + tg];
      pa[2] = pw[rpa + base + 4 + tg];
      pa[3] = pw[rpb + base + 4 + tg];
      const int k2a = base + tg, k2b = base + 4 + tg;
      const int swa = 4 * (k2a & 15), swb = 4 * (k2b & 15);
      #pragma unroll
      for (int j = 0; j < 8; ++j) {
        const int d = 8 * j + gid;
        uint32_t b0 = vb[k2a * 68 + ((d + swa) & 63)];
        uint32_t b1 = vb[k2b * 68 + ((d + swb) & 63)];
        mma16(oc[j], pa, b0, b1);
      }
    }
  }

  // ---- W zero tail ----
  {
    const int ktend = nkt * KT;
    const int r = tid >> 3, f = tid & 7;
    float4* wrow = (float4*)(Wg + (size_t)r * S_DIM);
    const float4 z = make_float4(0.f, 0.f, 0.f, 0.f);
    for (int c4 = (ktend >> 2) + f; c4 < (S_DIM >> 2); c4 += 8) wrow[c4] = z;
  }

  // ---- O merge: 4 k-slice partials per atom via smem reuse ----
  __syncthreads();
  float* smf = (float*)smw;
  {
    float* osc = &smf[w * (16 * 66)];   // warp's 16 rows x 64 d (+2 pad)
    #pragma unroll
    for (int j = 0; j < 8; ++j) {
      *(float2*)&osc[gid * 66 + j * 8 + 2 * tg]       = make_float2(oc[j][0], oc[j][1]);
      *(float2*)&osc[(gid + 8) * 66 + j * 8 + 2 * tg] = make_float2(oc[j][2], oc[j][3]);
    }
  }
  __syncthreads();
  #pragma unroll
  for (int it = 0; it < 8; ++it) {
    const int e = tid + it * NTHR;
    const int r = e >> 6, d = e & 63;         // r 0..31
    const int wbase = (r >> 4) * 4;           // atom -> warps [wbase, wbase+4)
    const int rl = r & 15;
    float s = 0.f;
    #pragma unroll
    for (int p = 0; p < 4; ++p) s += smf[(wbase + p) * (16 * 66) + rl * 66 + d];
    Og[r * 64 + d] = s;
  }
}

extern "C" void kernel_launch(void* const* d_in, const int* in_sizes, int n_in,
                              void* d_out, int out_size) {
  (void)in_sizes; (void)n_in; (void)out_size;
  const float* q = (const float*)d_in[0];
  const float* k = (const float*)d_in[1];
  const float* v = (const float*)d_in[2];
  float* out = (float*)d_out;

  cudaFuncSetAttribute(rowsum_kernel,
                       cudaFuncAttributeMaxDynamicSharedMemorySize, A_SMB);
  cudaFuncSetAttribute(attn_pb_kernel,
                       cudaFuncAttributeMaxDynamicSharedMemorySize, B_SMB);
  dim3 grid(S_DIM / QT, 32);
  kv_prep_kernel<<<KV_ELEMS / 4 / 256, 256>>>(k, v);
  rowsum_kernel<<<grid, NTHR, A_SMB>>>(q);
  attn_pb_kernel<<<grid, NTHR, B_SMB>>>(q, out);
}